// round 6
// baseline (speedup 1.0000x reference)
#include <cuda_runtime.h>

#define G       180
#define NA      64
#define Bx      27
#define RMAX    13
#define NCELL   (Bx*Bx*Bx)   // 19683
#define SPLIT   2
#define THREADS 256
#define NWARP   (THREADS/32)
#define AH      0.2f
#define ROF     2.5f
#define RO2F    6.25f
#define VCELLF  0.008f
#define STRIDE  (SPLIT*THREADS)      // 512
#define BATCH   4
#define CSTEP   (BATCH*STRIDE)       // 2048 list positions per iteration
#define CHUNK   ((NCELL + THREADS - 1) / THREADS)   // 77 cells per thread in compaction
#define LISTMAX 10240                // >= max possible in-sphere cells

__device__ float        g_partial[NA * SPLIT * 128];
__device__ unsigned int g_count[NA];

__device__ __forceinline__ unsigned long long pk2(float lo, float hi) {
    unsigned long long r;
    asm("mov.b64 %0, {%1, %2};" : "=l"(r) : "f"(lo), "f"(hi));
    return r;
}
__device__ __forceinline__ void upk2(float& lo, float& hi, unsigned long long v) {
    asm("mov.b64 {%0, %1}, %2;" : "=f"(lo), "=f"(hi) : "l"(v));
}
__device__ __forceinline__ void fma2(unsigned long long& d,
                                     unsigned long long a, unsigned long long b) {
    asm("fma.rn.f32x2 %0, %1, %2, %0;" : "+l"(d) : "l"(a), "l"(b));
}
__device__ __forceinline__ unsigned long long mul2(unsigned long long a,
                                                   unsigned long long b) {
    unsigned long long r;
    asm("mul.rn.f32x2 %0, %1, %2;" : "=l"(r) : "l"(a), "l"(b));
    return r;
}

__global__ __launch_bounds__(THREADS, 1)
void proj_kernel(const float* __restrict__ rho, const float* __restrict__ pos,
                 const float* __restrict__ W, float* __restrict__ out)
{
    const int blk  = blockIdx.x;
    const int atom = blk >> 1;          // SPLIT = 2
    const int part = blk & 1;
    const int tid  = threadIdx.x;

    // tab[ij] = { rowbase (as int), x^2+y^2, x, y } ; ztab[k] = { z, zindex }
    __shared__ float4 tab[Bx * Bx];
    __shared__ float2 ztab[Bx];
    __shared__ unsigned short list[LISTMAX];
    __shared__ int   wsum[NWARP];
    __shared__ int   stot;
    __shared__ float sred[NWARP * 128];
    __shared__ unsigned int slast;

    const float px = pos[atom*3+0];
    const float py = pos[atom*3+1];
    const float pz = pos[atom*3+2];
    const float cmx = rintf(px / AH);
    const float cmy = rintf(py / AH);
    const float cmz = rintf(pz / AH);
    const int cx = (int)cmx, cy = (int)cmy, cz = (int)cmz;
    const float dx = px - AH * cmx;
    const float dy = py - AH * cmy;
    const float dz = pz - AH * cmz;

    for (int ij = tid; ij < Bx * Bx; ij += THREADS) {
        const int i = ij / Bx;
        const int j = ij - i * Bx;
        int vx = cx + (i - RMAX);  vx = (vx < 0) ? vx + G : (vx >= G ? vx - G : vx);
        int vy = cy + (j - RMAX);  vy = (vy < 0) ? vy + G : (vy >= G ? vy - G : vy);
        const float xs = (float)(i - RMAX) * AH - dx;
        const float ys = (float)(j - RMAX) * AH - dy;
        tab[ij] = make_float4(__int_as_float((vx * G + vy) * G),
                              xs * xs + ys * ys, xs, ys);
    }
    if (tid < Bx) {
        int vz = cz + (tid - RMAX);  vz = (vz < 0) ? vz + G : (vz >= G ? vz - G : vz);
        const float zs = (float)(tid - RMAX) * AH - dz;
        ztab[tid] = make_float2(zs, __int_as_float(vz));
    }
    __syncthreads();

    // ---- stream compaction of in-sphere cells (deterministic order) ----
    const int idx0 = tid * CHUNK;
    int cnt = 0;
    {
        int ij = idx0 / Bx;
        int k  = idx0 - ij * Bx;
        #pragma unroll 1
        for (int c = 0; c < CHUNK; c++) {
            if (idx0 + c < NCELL) {
                const float rr = tab[ij].y;
                const float z  = ztab[k].x;
                if (fmaf(z, z, rr) < RO2F) cnt++;
            }
            if (++k == Bx) { k = 0; ij++; }
        }
    }
    // block-wide exclusive scan of cnt (deterministic: pure integer adds)
    const int lane = tid & 31, warp = tid >> 5;
    int inc = cnt;
    #pragma unroll
    for (int d = 1; d < 32; d <<= 1) {
        int n = __shfl_up_sync(0xffffffffu, inc, d);
        if (lane >= d) inc += n;
    }
    if (lane == 31) wsum[warp] = inc;
    __syncthreads();
    if (tid == 0) {
        int s = 0;
        #pragma unroll
        for (int w = 0; w < NWARP; w++) { int t = wsum[w]; wsum[w] = s; s += t; }
        stot = s;
    }
    __syncthreads();
    int base = wsum[warp] + inc - cnt;
    {
        int ij = idx0 / Bx;
        int k  = idx0 - ij * Bx;
        #pragma unroll 1
        for (int c = 0; c < CHUNK; c++) {
            if (idx0 + c < NCELL) {
                const float rr = tab[ij].y;
                const float z  = ztab[k].x;
                if (fmaf(z, z, rr) < RO2F)
                    list[base++] = (unsigned short)((ij << 5) | k);
            }
            if (++k == Bx) { k = 0; ij++; }
        }
    }
    __syncthreads();

    const int ntot  = stot;
    const int niter = (ntot + CSTEP - 1) / CSTEP;

    // packed accumulators: c2[m*8+p] = (coef[m][2p], coef[m][2p+1])
    unsigned long long c2[64];
    #pragma unroll
    for (int v = 0; v < 64; v++) c2[v] = 0ull;

    const int tbase = part * THREADS + tid;

    for (int it = 0; it < niter; it++) {
        const int ibase = it * CSTEP + tbase;

        // ---- front-batched loads for 4 compacted cells ----
        float xb[BATCH], yb[BATCH], zb[BATCH], r2b[BATCH], srho[BATCH];
        bool vld[BATCH];
        #pragma unroll
        for (int s = 0; s < BATCH; s++) {
            const int p = ibase + s * STRIDE;
            const bool v = (p < ntot);
            const int e  = list[v ? p : 0];
            const int ij = e >> 5;
            const int k  = e & 31;
            const float4 t = tab[ij];
            const float2 zz = ztab[k];
            srho[s] = __ldg(rho + __float_as_int(t.x) + __float_as_int(zz.y));
            xb[s] = t.z;  yb[s] = t.w;  zb[s] = zz.x;
            r2b[s] = fmaf(zz.x, zz.x, t.y);
            vld[s] = v;
        }

        // ---- process the 4 cells (all in-sphere; flat control flow) ----
        #pragma unroll
        for (int s = 0; s < BATCH; s++) {
            const float r2  = r2b[s];
            const float inv = rsqrtf(fmaxf(r2, 1e-24f));
            const float r   = r2 * inv;
            const float u   = ROF - r;
            const float p0  = vld[s] ? r2 * u * u * srho[s] : 0.0f;
            const float xh = xb[s] * inv, yh = yb[s] * inv, zh = zb[s] * inv;
            const float xh2 = xh*xh, yh2 = yh*yh, zh2 = zh*zh;

            unsigned long long yp[8];
            {
                const float Y0  = 0.28209479177387814f;
                const float Y1  = 0.4886025119029199f * yh;
                const float Y2  = 0.4886025119029199f * zh;
                const float Y3  = 0.4886025119029199f * xh;
                const float Y4  = 1.0925484305920792f * xh * yh;
                const float Y5  = 1.0925484305920792f * yh * zh;
                const float Y6  = 0.31539156525252005f * (3.0f * zh2 - 1.0f);
                const float Y7  = 1.0925484305920792f * xh * zh;
                const float Y8  = 0.5462742152960396f * (xh2 - yh2);
                const float Y9  = 0.5900435899266435f * yh * (3.0f * xh2 - yh2);
                const float Y10 = 2.890611442640554f  * xh * yh * zh;
                const float Y11 = 0.4570457994644658f * yh * (5.0f * zh2 - 1.0f);
                const float Y12 = 0.3731763325901154f * zh * (5.0f * zh2 - 3.0f);
                const float Y13 = 0.4570457994644658f * xh * (5.0f * zh2 - 1.0f);
                const float Y14 = 1.445305721320277f  * zh * (xh2 - yh2);
                const float Y15 = 0.5900435899266435f * xh * (xh2 - 3.0f * yh2);
                yp[0] = pk2(Y0,  Y1);  yp[1] = pk2(Y2,  Y3);
                yp[2] = pk2(Y4,  Y5);  yp[3] = pk2(Y6,  Y7);
                yp[4] = pk2(Y8,  Y9);  yp[5] = pk2(Y10, Y11);
                yp[6] = pk2(Y12, Y13); yp[7] = pk2(Y14, Y15);
            }

            unsigned long long tp = pk2(p0, p0);
            const unsigned long long up = pk2(u, u);
            #pragma unroll
            for (int m = 0; m < 8; m++) {
                #pragma unroll
                for (int q = 0; q < 8; q++)
                    fma2(c2[m*8 + q], tp, yp[q]);
                if (m < 7) tp = mul2(tp, up);
            }
        }
    }

    // ---- warp shuffle reduction -> smem -> block sum ----
    #pragma unroll
    for (int v = 0; v < 64; v++) {
        float lo, hi;
        upk2(lo, hi, c2[v]);
        lo += __shfl_down_sync(0xffffffffu, lo, 16);
        hi += __shfl_down_sync(0xffffffffu, hi, 16);
        lo += __shfl_down_sync(0xffffffffu, lo, 8);
        hi += __shfl_down_sync(0xffffffffu, hi, 8);
        lo += __shfl_down_sync(0xffffffffu, lo, 4);
        hi += __shfl_down_sync(0xffffffffu, hi, 4);
        lo += __shfl_down_sync(0xffffffffu, lo, 2);
        hi += __shfl_down_sync(0xffffffffu, hi, 2);
        lo += __shfl_down_sync(0xffffffffu, lo, 1);
        hi += __shfl_down_sync(0xffffffffu, hi, 1);
        if (lane == 0) {
            sred[warp * 128 + 2*v]     = lo;
            sred[warp * 128 + 2*v + 1] = hi;
        }
    }
    __syncthreads();

    if (tid < 128) {
        float s = 0.0f;
        #pragma unroll
        for (int w = 0; w < NWARP; w++) s += sred[w * 128 + tid];
        g_partial[blk * 128 + tid] = s;
    }
    __threadfence();
    __syncthreads();

    if (tid == 0) {
        const unsigned int ticket = atomicAdd(&g_count[atom], 1u);
        slast = (ticket == SPLIT - 1) ? 1u : 0u;
    }
    __syncthreads();

    if (slast) {
        const volatile float* gp = g_partial;
        if (tid < 128) {
            float s = 0.0f;
            #pragma unroll
            for (int p = 0; p < SPLIT; p++)
                s += gp[(atom * SPLIT + p) * 128 + tid];
            sred[tid] = s;
        }
        __syncthreads();
        if (tid < 128) {
            const int n = tid >> 4;
            const int q = tid & 15;
            float o = 0.0f;
            #pragma unroll
            for (int m = 0; m < 8; m++)
                o = fmaf(W[n * 8 + m], sred[m * 16 + q], o);
            out[atom * 128 + tid] = o * VCELLF;
        }
        if (tid == 0) g_count[atom] = 0u;
    }
}

extern "C" void kernel_launch(void* const* d_in, const int* in_sizes, int n_in,
                              void* d_out, int out_size)
{
    const float* rho = (const float*)d_in[0];   // 180^3
    const float* pos = (const float*)d_in[1];   // 64 x 3
    const float* W   = (const float*)d_in[2];   // 8 x 8
    float* out = (float*)d_out;                 // 64 x 128

    proj_kernel<<<NA * SPLIT, THREADS>>>(rho, pos, W, out);
}

// round 7
// speedup vs baseline: 1.4067x; 1.4067x over previous
#include <cuda_runtime.h>

#define G       180
#define NA      64
#define Bx      27
#define RMAX    13
#define NCELL   (Bx*Bx*Bx)   // 19683
#define SPLIT   2
#define THREADS 256
#define NWARP   (THREADS/32)
#define AH      0.2f
#define ROF     2.5f
#define RO2F    6.25f
#define VCELLF  0.008f
#define STRIDE  (SPLIT*THREADS)      // 512
#define BATCH   4
#define CSTEP   (BATCH*STRIDE)       // 2048 cells per iteration
#define NITER   ((NCELL + CSTEP - 1) / CSTEP)   // 10

__device__ float        g_partial[NA * SPLIT * 128];
__device__ unsigned int g_count[NA];

__device__ __forceinline__ unsigned long long pk2(float lo, float hi) {
    unsigned long long r;
    asm("mov.b64 %0, {%1, %2};" : "=l"(r) : "f"(lo), "f"(hi));
    return r;
}
__device__ __forceinline__ void upk2(float& lo, float& hi, unsigned long long v) {
    asm("mov.b64 {%0, %1}, %2;" : "=f"(lo), "=f"(hi) : "l"(v));
}
__device__ __forceinline__ void fma2(unsigned long long& d,
                                     unsigned long long a, unsigned long long b) {
    asm("fma.rn.f32x2 %0, %1, %2, %0;" : "+l"(d) : "l"(a), "l"(b));
}
__device__ __forceinline__ unsigned long long mul2(unsigned long long a,
                                                   unsigned long long b) {
    unsigned long long r;
    asm("mul.rn.f32x2 %0, %1, %2;" : "=l"(r) : "l"(a), "l"(b));
    return r;
}

__global__ __launch_bounds__(THREADS, 1)
void proj_kernel(const float* __restrict__ rho, const float* __restrict__ pos,
                 const float* __restrict__ W, float* __restrict__ out)
{
    const int blk  = blockIdx.x;
    const int atom = blk >> 1;          // SPLIT = 2
    const int part = blk & 1;
    const int tid  = threadIdx.x;

    // tab[ij] = { rowbase (as int), x^2+y^2, x, y } ; ztab[k] = { z, zindex }
    __shared__ float4 tab[Bx * Bx];
    __shared__ float2 ztab[Bx];
    __shared__ float  sred[NWARP * 128];
    __shared__ unsigned int slast;

    const float px = pos[atom*3+0];
    const float py = pos[atom*3+1];
    const float pz = pos[atom*3+2];
    const float cmx = rintf(px / AH);
    const float cmy = rintf(py / AH);
    const float cmz = rintf(pz / AH);
    const int cx = (int)cmx, cy = (int)cmy, cz = (int)cmz;
    const float dx = px - AH * cmx;
    const float dy = py - AH * cmy;
    const float dz = pz - AH * cmz;

    for (int ij = tid; ij < Bx * Bx; ij += THREADS) {
        const int i = ij / Bx;
        const int j = ij - i * Bx;
        int vx = cx + (i - RMAX);  vx = (vx < 0) ? vx + G : (vx >= G ? vx - G : vx);
        int vy = cy + (j - RMAX);  vy = (vy < 0) ? vy + G : (vy >= G ? vy - G : vy);
        const float xs = (float)(i - RMAX) * AH - dx;
        const float ys = (float)(j - RMAX) * AH - dy;
        tab[ij] = make_float4(__int_as_float((vx * G + vy) * G),
                              xs * xs + ys * ys, xs, ys);
    }
    if (tid < Bx) {
        int vz = cz + (tid - RMAX);  vz = (vz < 0) ? vz + G : (vz >= G ? vz - G : vz);
        const float zs = (float)(tid - RMAX) * AH - dz;
        ztab[tid] = make_float2(zs, __int_as_float(vz));
    }
    __syncthreads();

    // packed accumulators: c2[m*8+p] = (coef[m][2p], coef[m][2p+1])
    unsigned long long c2[64];
    #pragma unroll
    for (int v = 0; v < 64; v++) c2[v] = 0ull;

    const int tbase = part * THREADS + tid;

    // ---- prefetch srho + packed cell index for batch 0 (LDG only) ----
    float sra[BATCH];
    int   ea[BATCH];     // (ij<<5)|k, or -1 if out of range
    #pragma unroll
    for (int s = 0; s < BATCH; s++) {
        const int id = tbase + s * STRIDE;
        const bool v = (id < NCELL);
        const int iid = v ? id : 0;
        const int ij = iid / Bx;
        const int k  = iid - ij * Bx;
        const int rowbase = __float_as_int(tab[ij].x);
        const int zidx    = __float_as_int(ztab[k].y);
        sra[s] = __ldg(rho + rowbase + zidx);
        ea[s]  = v ? ((ij << 5) | k) : -1;
    }

    #pragma unroll 1
    for (int it = 0; it < NITER; it++) {
        // ---- prefetch next batch's srho (addresses via 2 scalar LDS each) ----
        float srb[BATCH];
        int   eb[BATCH];
        if (it + 1 < NITER) {
            const int nbase = (it + 1) * CSTEP + tbase;
            #pragma unroll
            for (int s = 0; s < BATCH; s++) {
                const int id = nbase + s * STRIDE;
                const bool v = (id < NCELL);
                const int iid = v ? id : 0;
                const int ij = iid / Bx;
                const int k  = iid - ij * Bx;
                const int rowbase = __float_as_int(tab[ij].x);
                const int zidx    = __float_as_int(ztab[k].y);
                srb[s] = __ldg(rho + rowbase + zidx);
                eb[s]  = v ? ((ij << 5) | k) : -1;
            }
        } else {
            #pragma unroll
            for (int s = 0; s < BATCH; s++) { srb[s] = 0.0f; eb[s] = -1; }
        }

        // ---- geometry for current batch from smem ----
        float4 t4[BATCH];  float2 z2[BATCH];
        #pragma unroll
        for (int s = 0; s < BATCH; s++) {
            const int e = (ea[s] < 0) ? 0 : ea[s];
            t4[s] = tab[e >> 5];
            z2[s] = ztab[e & 31];
        }

        // ---- process current batch ----
        #pragma unroll
        for (int s = 0; s < BATCH; s++) {
            const float x = t4[s].z, y = t4[s].w, z = z2[s].x;
            const float r2 = fmaf(z, z, t4[s].y);
            const bool valid = (ea[s] >= 0) && (r2 < RO2F);
            if (__ballot_sync(0xffffffffu, valid) == 0u) continue;  // warp-uniform

            const float inv = rsqrtf(fmaxf(r2, 1e-24f));
            const float r   = r2 * inv;
            const float u   = ROF - r;
            const float p0  = valid ? r2 * u * u * sra[s] : 0.0f;
            const float xh = x * inv, yh = y * inv, zh = z * inv;
            const float xh2 = xh*xh, yh2 = yh*yh, zh2 = zh*zh;

            unsigned long long yp[8];
            {
                const float Y0  = 0.28209479177387814f;
                const float Y1  = 0.4886025119029199f * yh;
                const float Y2  = 0.4886025119029199f * zh;
                const float Y3  = 0.4886025119029199f * xh;
                const float Y4  = 1.0925484305920792f * xh * yh;
                const float Y5  = 1.0925484305920792f * yh * zh;
                const float Y6  = 0.31539156525252005f * (3.0f * zh2 - 1.0f);
                const float Y7  = 1.0925484305920792f * xh * zh;
                const float Y8  = 0.5462742152960396f * (xh2 - yh2);
                const float Y9  = 0.5900435899266435f * yh * (3.0f * xh2 - yh2);
                const float Y10 = 2.890611442640554f  * xh * yh * zh;
                const float Y11 = 0.4570457994644658f * yh * (5.0f * zh2 - 1.0f);
                const float Y12 = 0.3731763325901154f * zh * (5.0f * zh2 - 3.0f);
                const float Y13 = 0.4570457994644658f * xh * (5.0f * zh2 - 1.0f);
                const float Y14 = 1.445305721320277f  * zh * (xh2 - yh2);
                const float Y15 = 0.5900435899266435f * xh * (xh2 - 3.0f * yh2);
                yp[0] = pk2(Y0,  Y1);  yp[1] = pk2(Y2,  Y3);
                yp[2] = pk2(Y4,  Y5);  yp[3] = pk2(Y6,  Y7);
                yp[4] = pk2(Y8,  Y9);  yp[5] = pk2(Y10, Y11);
                yp[6] = pk2(Y12, Y13); yp[7] = pk2(Y14, Y15);
            }

            unsigned long long tp = pk2(p0, p0);
            const unsigned long long up = pk2(u, u);
            #pragma unroll
            for (int m = 0; m < 8; m++) {
                #pragma unroll
                for (int q = 0; q < 8; q++)
                    fma2(c2[m*8 + q], tp, yp[q]);
                if (m < 7) tp = mul2(tp, up);
            }
        }

        // ---- rotate prefetched srho ----
        #pragma unroll
        for (int s = 0; s < BATCH; s++) { sra[s] = srb[s]; ea[s] = eb[s]; }
    }

    // ---- warp shuffle reduction -> smem -> block sum ----
    const int lane = tid & 31, warp = tid >> 5;
    #pragma unroll
    for (int v = 0; v < 64; v++) {
        float lo, hi;
        upk2(lo, hi, c2[v]);
        lo += __shfl_down_sync(0xffffffffu, lo, 16);
        hi += __shfl_down_sync(0xffffffffu, hi, 16);
        lo += __shfl_down_sync(0xffffffffu, lo, 8);
        hi += __shfl_down_sync(0xffffffffu, hi, 8);
        lo += __shfl_down_sync(0xffffffffu, lo, 4);
        hi += __shfl_down_sync(0xffffffffu, hi, 4);
        lo += __shfl_down_sync(0xffffffffu, lo, 2);
        hi += __shfl_down_sync(0xffffffffu, hi, 2);
        lo += __shfl_down_sync(0xffffffffu, lo, 1);
        hi += __shfl_down_sync(0xffffffffu, hi, 1);
        if (lane == 0) {
            sred[warp * 128 + 2*v]     = lo;
            sred[warp * 128 + 2*v + 1] = hi;
        }
    }
    __syncthreads();

    if (tid < 128) {
        float s = 0.0f;
        #pragma unroll
        for (int w = 0; w < NWARP; w++) s += sred[w * 128 + tid];
        g_partial[blk * 128 + tid] = s;
    }
    __threadfence();
    __syncthreads();

    if (tid == 0) {
        const unsigned int ticket = atomicAdd(&g_count[atom], 1u);
        slast = (ticket == SPLIT - 1) ? 1u : 0u;
    }
    __syncthreads();

    if (slast) {
        const volatile float* gp = g_partial;
        if (tid < 128) {
            float s = 0.0f;
            #pragma unroll
            for (int p = 0; p < SPLIT; p++)
                s += gp[(atom * SPLIT + p) * 128 + tid];
            sred[tid] = s;
        }
        __syncthreads();
        if (tid < 128) {
            const int n = tid >> 4;
            const int q = tid & 15;
            float o = 0.0f;
            #pragma unroll
            for (int m = 0; m < 8; m++)
                o = fmaf(W[n * 8 + m], sred[m * 16 + q], o);
            out[atom * 128 + tid] = o * VCELLF;
        }
        if (tid == 0) g_count[atom] = 0u;
    }
}

extern "C" void kernel_launch(void* const* d_in, const int* in_sizes, int n_in,
                              void* d_out, int out_size)
{
    const float* rho = (const float*)d_in[0];   // 180^3
    const float* pos = (const float*)d_in[1];   // 64 x 3
    const float* W   = (const float*)d_in[2];   // 8 x 8
    float* out = (float*)d_out;                 // 64 x 128

    proj_kernel<<<NA * SPLIT, THREADS>>>(rho, pos, W, out);
}

// round 8
// speedup vs baseline: 1.5333x; 1.0900x over previous
#include <cuda_runtime.h>

#define G       180
#define NA      64
#define Bx      27
#define RMAX    13
#define SPLIT   2
#define THREADS 384
#define NWARP   (THREADS/32)     // 12
#define AH      0.2f
#define ROF     2.5f
#define RO2F    6.25f
#define VCELLF  0.008f
#define NCOL    (Bx*Bx)          // 729

__device__ float        g_partial[NA * SPLIT * 128];
__device__ unsigned int g_count[NA];

__device__ __forceinline__ unsigned long long pk2(float lo, float hi) {
    unsigned long long r;
    asm("mov.b64 %0, {%1, %2};" : "=l"(r) : "f"(lo), "f"(hi));
    return r;
}
__device__ __forceinline__ void upk2(float& lo, float& hi, unsigned long long v) {
    asm("mov.b64 {%0, %1}, %2;" : "=f"(lo), "=f"(hi) : "l"(v));
}
__device__ __forceinline__ void fma2(unsigned long long& d,
                                     unsigned long long a, unsigned long long b) {
    asm("fma.rn.f32x2 %0, %1, %2, %0;" : "+l"(d) : "l"(a), "l"(b));
}
__device__ __forceinline__ unsigned long long mul2(unsigned long long a,
                                                   unsigned long long b) {
    unsigned long long r;
    asm("mul.rn.f32x2 %0, %1, %2;" : "=l"(r) : "l"(a), "l"(b));
    return r;
}

__global__ __launch_bounds__(THREADS)
void proj_kernel(const float* __restrict__ rho, const float* __restrict__ pos,
                 const float* __restrict__ W, float* __restrict__ out)
{
    const int blk  = blockIdx.x;
    const int atom = blk >> 1;          // SPLIT = 2
    const int part = blk & 1;
    const int tid  = threadIdx.x;

    __shared__ float2 ztab[Bx];         // { z, zindex(asfloat) }
    __shared__ float  sred[NWARP * 128];
    __shared__ unsigned int slast;

    const float px = pos[atom*3+0];
    const float py = pos[atom*3+1];
    const float pz = pos[atom*3+2];
    const float cmx = rintf(px * 5.0f);
    const float cmy = rintf(py * 5.0f);
    const float cmz = rintf(pz * 5.0f);
    const int cx = (int)cmx, cy = (int)cmy, cz = (int)cmz;
    const float dx = px - AH * cmx;
    const float dy = py - AH * cmy;
    const float dz = pz - AH * cmz;

    if (tid < Bx) {
        int vz = cz + (tid - RMAX);
        vz += (vz < 0) ? G : 0;  vz -= (vz >= G) ? G : 0;
        const float zs = (float)(tid - RMAX) * AH - dz;
        ztab[tid] = make_float2(zs, __int_as_float(vz));
    }
    __syncthreads();

    // ---- ring-ordered column assignment: column index c = 2*tid + part ----
    const int cidx   = 2 * tid + part;
    const bool activ = (cidx < NCOL);
    const int cc     = activ ? cidx : 0;

    int i, j;
    {
        const float rf = sqrtf((float)cc);
        const int rr = (int)((rf + 1.0f) * 0.5f);      // square-ring index
        if (rr == 0) { i = RMAX; j = RMAX; }
        else {
            const int t    = cc - (2*rr - 1) * (2*rr - 1);
            const int side = t / (2*rr);
            const int posn = t - side * (2*rr);
            if      (side == 0) { i = RMAX - rr;        j = RMAX - rr + posn; }
            else if (side == 1) { i = RMAX - rr + posn; j = RMAX + rr; }
            else if (side == 2) { i = RMAX + rr;        j = RMAX + rr - posn; }
            else                { i = RMAX + rr - posn; j = RMAX - rr; }
        }
    }

    // ---- per-column constants ----
    const int di = i - RMAX, dj = j - RMAX;
    int vx = cx + di;  vx += (vx < 0) ? G : 0;  vx -= (vx >= G) ? G : 0;
    int vy = cy + dj;  vy += (vy < 0) ? G : 0;  vy -= (vy >= G) ? G : 0;
    const int rowbase = (vx * G + vy) * G;
    const float x   = (float)di * AH - dx;
    const float y   = (float)dj * AH - dy;
    const float c2d = x * x + y * y;
    const float s2  = RO2F - c2d;

    int kmin = 1, kmax = 0;
    if (activ && s2 > 0.0f) {
        const float sq = sqrtf(s2);
        kmin = max(0,  (int)floorf(13.0f + (dz - sq) * 5.0f));
        kmax = min(26, (int)ceilf (13.0f + (dz + sq) * 5.0f));
    }

    // packed accumulators: c2a[m*8+p] = (coef[m][2p], coef[m][2p+1])
    unsigned long long c2a[64];
    #pragma unroll
    for (int v = 0; v < 64; v++) c2a[v] = 0ull;

    if (kmin <= kmax) {
        // rolling prefetch of ztab entry + rho value
        float2 zz = ztab[kmin];
        float  sr = __ldg(rho + rowbase + __float_as_int(zz.y));

        #pragma unroll 1
        for (int k = kmin; k <= kmax; k++) {
            const float z    = zz.x;
            const float srho = sr;
            if (k < kmax) {
                zz = ztab[k + 1];
                sr = __ldg(rho + rowbase + __float_as_int(zz.y));
            }

            const float r2  = fmaf(z, z, c2d);
            const float inv = rsqrtf(fmaxf(r2, 1e-24f));
            const float r   = r2 * inv;
            const float u   = fmaxf(ROF - r, 0.0f);   // clamps out-of-range cells to 0
            const float p0  = r2 * u * u * srho;
            const float xh = x * inv, yh = y * inv, zh = z * inv;
            const float xh2 = xh*xh, yh2 = yh*yh, zh2 = zh*zh;

            unsigned long long yp[8];
            {
                const float Y0  = 0.28209479177387814f;
                const float Y1  = 0.4886025119029199f * yh;
                const float Y2  = 0.4886025119029199f * zh;
                const float Y3  = 0.4886025119029199f * xh;
                const float Y4  = 1.0925484305920792f * xh * yh;
                const float Y5  = 1.0925484305920792f * yh * zh;
                const float Y6  = 0.31539156525252005f * (3.0f * zh2 - 1.0f);
                const float Y7  = 1.0925484305920792f * xh * zh;
                const float Y8  = 0.5462742152960396f * (xh2 - yh2);
                const float Y9  = 0.5900435899266435f * yh * (3.0f * xh2 - yh2);
                const float Y10 = 2.890611442640554f  * xh * yh * zh;
                const float Y11 = 0.4570457994644658f * yh * (5.0f * zh2 - 1.0f);
                const float Y12 = 0.3731763325901154f * zh * (5.0f * zh2 - 3.0f);
                const float Y13 = 0.4570457994644658f * xh * (5.0f * zh2 - 1.0f);
                const float Y14 = 1.445305721320277f  * zh * (xh2 - yh2);
                const float Y15 = 0.5900435899266435f * xh * (xh2 - 3.0f * yh2);
                yp[0] = pk2(Y0,  Y1);  yp[1] = pk2(Y2,  Y3);
                yp[2] = pk2(Y4,  Y5);  yp[3] = pk2(Y6,  Y7);
                yp[4] = pk2(Y8,  Y9);  yp[5] = pk2(Y10, Y11);
                yp[6] = pk2(Y12, Y13); yp[7] = pk2(Y14, Y15);
            }

            unsigned long long tp = pk2(p0, p0);
            const unsigned long long up = pk2(u, u);
            #pragma unroll
            for (int m = 0; m < 8; m++) {
                #pragma unroll
                for (int q = 0; q < 8; q++)
                    fma2(c2a[m*8 + q], tp, yp[q]);
                if (m < 7) tp = mul2(tp, up);
            }
        }
    }

    // ---- warp shuffle reduction -> smem -> block sum ----
    const int lane = tid & 31, warp = tid >> 5;
    #pragma unroll
    for (int v = 0; v < 64; v++) {
        float lo, hi;
        upk2(lo, hi, c2a[v]);
        lo += __shfl_down_sync(0xffffffffu, lo, 16);
        hi += __shfl_down_sync(0xffffffffu, hi, 16);
        lo += __shfl_down_sync(0xffffffffu, lo, 8);
        hi += __shfl_down_sync(0xffffffffu, hi, 8);
        lo += __shfl_down_sync(0xffffffffu, lo, 4);
        hi += __shfl_down_sync(0xffffffffu, hi, 4);
        lo += __shfl_down_sync(0xffffffffu, lo, 2);
        hi += __shfl_down_sync(0xffffffffu, hi, 2);
        lo += __shfl_down_sync(0xffffffffu, lo, 1);
        hi += __shfl_down_sync(0xffffffffu, hi, 1);
        if (lane == 0) {
            sred[warp * 128 + 2*v]     = lo;
            sred[warp * 128 + 2*v + 1] = hi;
        }
    }
    __syncthreads();

    if (tid < 128) {
        float s = 0.0f;
        #pragma unroll
        for (int w = 0; w < NWARP; w++) s += sred[w * 128 + tid];
        g_partial[blk * 128 + tid] = s;
    }
    __threadfence();
    __syncthreads();

    if (tid == 0) {
        const unsigned int ticket = atomicAdd(&g_count[atom], 1u);
        slast = (ticket == SPLIT - 1) ? 1u : 0u;
    }
    __syncthreads();

    if (slast) {
        const volatile float* gp = g_partial;
        if (tid < 128) {
            float s = 0.0f;
            #pragma unroll
            for (int p = 0; p < SPLIT; p++)
                s += gp[(atom * SPLIT + p) * 128 + tid];
            sred[tid] = s;
        }
        __syncthreads();
        if (tid < 128) {
            const int n = tid >> 4;
            const int q = tid & 15;
            float o = 0.0f;
            #pragma unroll
            for (int m = 0; m < 8; m++)
                o = fmaf(W[n * 8 + m], sred[m * 16 + q], o);
            out[atom * 128 + tid] = o * VCELLF;
        }
        if (tid == 0) g_count[atom] = 0u;
    }
}

extern "C" void kernel_launch(void* const* d_in, const int* in_sizes, int n_in,
                              void* d_out, int out_size)
{
    const float* rho = (const float*)d_in[0];   // 180^3
    const float* pos = (const float*)d_in[1];   // 64 x 3
    const float* W   = (const float*)d_in[2];   // 8 x 8
    float* out = (float*)d_out;                 // 64 x 128

    proj_kernel<<<NA * SPLIT, THREADS>>>(rho, pos, W, out);
}

// round 10
// speedup vs baseline: 1.7196x; 1.1215x over previous
#include <cuda_runtime.h>

#define G       180
#define NA      64
#define Bx      27
#define RMAX    13
#define SPLIT   2
#define THREADS 384
#define NWARP   (THREADS/32)     // 12
#define AH      0.2f
#define ROF     2.5f
#define RO2F    6.25f
#define VCELLF  0.008f
#define NCOL    (Bx*Bx)          // 729
#define ROWS    (NWARP*16)       // 192 staged rows
#define RSTR    136              // padded row stride (floats), 16B aligned
#define DSMEM   (ROWS*RSTR*4)    // 104448 bytes

__device__ float        g_partial[NA * SPLIT * 128];
__device__ unsigned int g_count[NA];

__device__ __forceinline__ unsigned long long pk2(float lo, float hi) {
    unsigned long long r;
    asm("mov.b64 %0, {%1, %2};" : "=l"(r) : "f"(lo), "f"(hi));
    return r;
}
__device__ __forceinline__ void upk2(float& lo, float& hi, unsigned long long v) {
    asm("mov.b64 {%0, %1}, %2;" : "=f"(lo), "=f"(hi) : "l"(v));
}
__device__ __forceinline__ void fma2(unsigned long long& d,
                                     unsigned long long a, unsigned long long b) {
    asm("fma.rn.f32x2 %0, %1, %2, %0;" : "+l"(d) : "l"(a), "l"(b));
}
__device__ __forceinline__ unsigned long long mul2(unsigned long long a,
                                                   unsigned long long b) {
    unsigned long long r;
    asm("mul.rn.f32x2 %0, %1, %2;" : "=l"(r) : "l"(a), "l"(b));
    return r;
}

extern __shared__ float dynbuf[];   // ROWS x RSTR floats

__device__ __forceinline__ void cell_update(unsigned long long* c2a,
                                            float x, float y, float z,
                                            float c2d, float srho)
{
    const float r2  = fmaf(z, z, c2d);
    const float inv = rsqrtf(fmaxf(r2, 1e-24f));
    const float r   = r2 * inv;
    const float u   = fmaxf(ROF - r, 0.0f);    // zero outside cutoff
    const float p0  = r2 * u * u * srho;
    const float xh = x * inv, yh = y * inv, zh = z * inv;
    const float xh2 = xh*xh, yh2 = yh*yh, zh2 = zh*zh;

    unsigned long long yp[8];
    {
        const float Y0  = 0.28209479177387814f;
        const float Y1  = 0.4886025119029199f * yh;
        const float Y2  = 0.4886025119029199f * zh;
        const float Y3  = 0.4886025119029199f * xh;
        const float Y4  = 1.0925484305920792f * xh * yh;
        const float Y5  = 1.0925484305920792f * yh * zh;
        const float Y6  = 0.31539156525252005f * (3.0f * zh2 - 1.0f);
        const float Y7  = 1.0925484305920792f * xh * zh;
        const float Y8  = 0.5462742152960396f * (xh2 - yh2);
        const float Y9  = 0.5900435899266435f * yh * (3.0f * xh2 - yh2);
        const float Y10 = 2.890611442640554f  * xh * yh * zh;
        const float Y11 = 0.4570457994644658f * yh * (5.0f * zh2 - 1.0f);
        const float Y12 = 0.3731763325901154f * zh * (5.0f * zh2 - 3.0f);
        const float Y13 = 0.4570457994644658f * xh * (5.0f * zh2 - 1.0f);
        const float Y14 = 1.445305721320277f  * zh * (xh2 - yh2);
        const float Y15 = 0.5900435899266435f * xh * (xh2 - 3.0f * yh2);
        yp[0] = pk2(Y0,  Y1);  yp[1] = pk2(Y2,  Y3);
        yp[2] = pk2(Y4,  Y5);  yp[3] = pk2(Y6,  Y7);
        yp[4] = pk2(Y8,  Y9);  yp[5] = pk2(Y10, Y11);
        yp[6] = pk2(Y12, Y13); yp[7] = pk2(Y14, Y15);
    }

    unsigned long long tp = pk2(p0, p0);
    const unsigned long long up = pk2(u, u);
    #pragma unroll
    for (int m = 0; m < 8; m++) {
        #pragma unroll
        for (int q = 0; q < 8; q++)
            fma2(c2a[m*8 + q], tp, yp[q]);
        if (m < 7) tp = mul2(tp, up);
    }
}

__global__ __launch_bounds__(THREADS)
void proj_kernel(const float* __restrict__ rho, const float* __restrict__ pos,
                 const float* __restrict__ W, float* __restrict__ out)
{
    const int blk  = blockIdx.x;
    const int atom = blk >> 1;          // SPLIT = 2
    const int part = blk & 1;
    const int tid  = threadIdx.x;

    __shared__ float2 ztab[32];         // { z, zindex(asfloat) }, padded
    __shared__ float  spart[3 * 128];
    __shared__ unsigned int slast;

    const float px = pos[atom*3+0];
    const float py = pos[atom*3+1];
    const float pz = pos[atom*3+2];
    const float cmx = rintf(px * 5.0f);
    const float cmy = rintf(py * 5.0f);
    const float cmz = rintf(pz * 5.0f);
    const int cx = (int)cmx, cy = (int)cmy, cz = (int)cmz;
    const float dx = px - AH * cmx;
    const float dy = py - AH * cmy;
    const float dz = pz - AH * cmz;

    if (tid < 32) {
        const int kk = min(tid, Bx - 1);          // pad 27..31 with k=26
        int vz = cz + (kk - RMAX);
        vz += (vz < 0) ? G : 0;  vz -= (vz >= G) ? G : 0;
        const float zs = (float)(kk - RMAX) * AH - dz;
        ztab[tid] = make_float2(zs, __int_as_float(vz));
    }
    __syncthreads();

    // ---- ring-ordered column assignment: column index c = 2*tid + part ----
    const int cidx   = 2 * tid + part;
    const bool activ = (cidx < NCOL);
    const int cc     = activ ? cidx : 0;

    int i, j;
    {
        const float rf = sqrtf((float)cc);
        const int rr = (int)((rf + 1.0f) * 0.5f);      // square-ring index
        if (rr == 0) { i = RMAX; j = RMAX; }
        else {
            const int t    = cc - (2*rr - 1) * (2*rr - 1);
            const int side = t / (2*rr);
            const int posn = t - side * (2*rr);
            if      (side == 0) { i = RMAX - rr;        j = RMAX - rr + posn; }
            else if (side == 1) { i = RMAX - rr + posn; j = RMAX + rr; }
            else if (side == 2) { i = RMAX + rr;        j = RMAX + rr - posn; }
            else                { i = RMAX + rr - posn; j = RMAX - rr; }
        }
    }

    // ---- per-column constants ----
    const int di = i - RMAX, dj = j - RMAX;
    int vx = cx + di;  vx += (vx < 0) ? G : 0;  vx -= (vx >= G) ? G : 0;
    int vy = cy + dj;  vy += (vy < 0) ? G : 0;  vy -= (vy >= G) ? G : 0;
    const int rowbase = (vx * G + vy) * G;
    const float x   = (float)di * AH - dx;
    const float y   = (float)dj * AH - dy;
    const float c2d = x * x + y * y;
    const float s2  = RO2F - c2d;

    int kmin = 1, kmax = 0;
    if (activ && s2 > 0.0f) {
        const float sq = sqrtf(s2);
        kmin = max(0,  (int)floorf(13.0f + (dz - sq) * 5.0f));
        kmax = min(26, (int)ceilf (13.0f + (dz + sq) * 5.0f));
    }

    // packed accumulators: c2a[m*8+p] = (coef[m][2p], coef[m][2p+1])
    unsigned long long c2a[64];
    #pragma unroll
    for (int v = 0; v < 64; v++) c2a[v] = 0ull;

    if (kmin <= kmax) {
        // distance-2 rolling prefetch (ztab padded so indices never branch)
        float2 zz0 = ztab[kmin];
        float2 zz1 = ztab[kmin + 1];
        float  sr0 = __ldg(rho + rowbase + __float_as_int(zz0.y));
        float  sr1 = __ldg(rho + rowbase + __float_as_int(zz1.y));

        #pragma unroll 1
        for (int k = kmin; k <= kmax; k += 2) {
            float2 nz0 = ztab[k + 2];
            float2 nz1 = ztab[k + 3];
            float  nr0 = __ldg(rho + rowbase + __float_as_int(nz0.y));
            float  nr1 = __ldg(rho + rowbase + __float_as_int(nz1.y));

            cell_update(c2a, x, y, zz0.x, c2d, sr0);
            const float m1 = (k + 1 <= kmax) ? 1.0f : 0.0f;
            cell_update(c2a, x, y, zz1.x, c2d, sr1 * m1);

            zz0 = nz0;  zz1 = nz1;  sr0 = nr0;  sr1 = nr1;
        }
    }

    // ---- one shfl fold (32 -> 16 lanes) ----
    const int lane = tid & 31, warp = tid >> 5;
    #pragma unroll
    for (int v = 0; v < 64; v++) {
        float lo, hi;
        upk2(lo, hi, c2a[v]);
        lo += __shfl_down_sync(0xffffffffu, lo, 16);
        hi += __shfl_down_sync(0xffffffffu, hi, 16);
        c2a[v] = pk2(lo, hi);
    }

    // ---- stage 192 rows x 128 floats to dynamic smem ----
    if (lane < 16) {
        float* dst = dynbuf + (warp * 16 + lane) * RSTR;
        #pragma unroll
        for (int v = 0; v < 64; v += 2)
            *reinterpret_cast<ulonglong2*>(dst + 2 * v) =
                make_ulonglong2(c2a[v], c2a[v + 1]);
    }
    __syncthreads();

    // ---- flat reduce: 3 threads per value, 64 rows each,
    //      8 interleaved stripes + pairwise combine (tree-like rounding) ----
    {
        const int v   = tid & 127;
        const int seg = tid >> 7;            // 0..2
        const float* src = dynbuf + (seg * 64) * RSTR + v;
        float a0=0,a1=0,a2=0,a3=0,a4=0,a5=0,a6=0,a7=0;
        #pragma unroll
        for (int r = 0; r < 64; r += 8) {
            a0 += src[(r+0) * RSTR];
            a1 += src[(r+1) * RSTR];
            a2 += src[(r+2) * RSTR];
            a3 += src[(r+3) * RSTR];
            a4 += src[(r+4) * RSTR];
            a5 += src[(r+5) * RSTR];
            a6 += src[(r+6) * RSTR];
            a7 += src[(r+7) * RSTR];
        }
        spart[seg * 128 + v] = ((a0 + a1) + (a2 + a3)) + ((a4 + a5) + (a6 + a7));
    }
    __syncthreads();

    if (tid < 128) {
        const float s = (spart[tid] + spart[128 + tid]) + spart[256 + tid];
        g_partial[blk * 128 + tid] = s;
    }
    __threadfence();
    __syncthreads();

    if (tid == 0) {
        const unsigned int ticket = atomicAdd(&g_count[atom], 1u);
        slast = (ticket == SPLIT - 1) ? 1u : 0u;
    }
    __syncthreads();

    if (slast) {
        const volatile float* gp = g_partial;
        if (tid < 128) {
            float s = 0.0f;
            #pragma unroll
            for (int p = 0; p < SPLIT; p++)
                s += gp[(atom * SPLIT + p) * 128 + tid];
            spart[tid] = s;
        }
        __syncthreads();
        if (tid < 128) {
            const int n = tid >> 4;
            const int q = tid & 15;
            float o = 0.0f;
            #pragma unroll
            for (int m = 0; m < 8; m++)
                o = fmaf(W[n * 8 + m], spart[m * 16 + q], o);
            out[atom * 128 + tid] = o * VCELLF;
        }
        if (tid == 0) g_count[atom] = 0u;
    }
}

extern "C" void kernel_launch(void* const* d_in, const int* in_sizes, int n_in,
                              void* d_out, int out_size)
{
    const float* rho = (const float*)d_in[0];   // 180^3
    const float* pos = (const float*)d_in[1];   // 64 x 3
    const float* W   = (const float*)d_in[2];   // 8 x 8
    float* out = (float*)d_out;                 // 64 x 128

    cudaFuncSetAttribute(proj_kernel,
                         cudaFuncAttributeMaxDynamicSharedMemorySize, DSMEM);
    proj_kernel<<<NA * SPLIT, THREADS, DSMEM>>>(rho, pos, W, out);
}